// round 11
// baseline (speedup 1.0000x reference)
#include <cuda_runtime.h>
#include <cuda_fp16.h>
#include <cstdint>

#define BATCH 2
#define SEQ   2048
#define DIM   1024
#define NH    16
#define HDIM  64
#define MTOT  (BATCH * SEQ)   // 4096

// ---------------------------------------------------------------------------
// Scratch (allocation-free __device__ globals), all fp16
// ---------------------------------------------------------------------------
__device__ __align__(16) __half g_Xh[(size_t)MTOT * DIM];
__device__ __align__(16) __half g_Oh[(size_t)MTOT * DIM];          // attn out
__device__ __align__(16) __half g_Wall[(size_t)3 * DIM * DIM];     // Wq|Wk|Wv
__device__ __align__(16) __half g_Wo_h[(size_t)DIM * DIM];
__device__ float g_bias[3 * DIM];

// attention operands, per-head layouts
__device__ __align__(16) __half g_Q[(size_t)BATCH * NH * SEQ * HDIM];
__device__ __align__(16) __half g_K[(size_t)BATCH * NH * SEQ * HDIM];
__device__ __align__(16) __half g_Vt[(size_t)BATCH * NH * HDIM * SEQ];

// ---------------------------------------------------------------------------
// PTX helpers (arch-neutral)
// ---------------------------------------------------------------------------
__device__ __forceinline__ uint32_t smem_u32(const void* p) {
    uint32_t a;
    asm("{ .reg .u64 t; cvta.to.shared.u64 t, %1; cvt.u32.u64 %0, t; }"
        : "=r"(a) : "l"(p));
    return a;
}
__device__ __forceinline__ void cp16(uint32_t dst, const void* src) {
    asm volatile("cp.async.cg.shared.global [%0], [%1], 16;" :: "r"(dst), "l"(src));
}
__device__ __forceinline__ void cp_commit() {
    asm volatile("cp.async.commit_group;" ::: "memory");
}
__device__ __forceinline__ void cp_wait0() {
    asm volatile("cp.async.wait_group 0;" ::: "memory");
}
__device__ __forceinline__ void cp_wait1() {
    asm volatile("cp.async.wait_group 1;" ::: "memory");
}
__device__ __forceinline__ void cp_wait2() {
    asm volatile("cp.async.wait_group 2;" ::: "memory");
}
__device__ __forceinline__ void ldsm4(uint32_t* r, uint32_t addr) {
    asm volatile("ldmatrix.sync.aligned.m8n8.x4.shared.b16 {%0,%1,%2,%3}, [%4];"
        : "=r"(r[0]), "=r"(r[1]), "=r"(r[2]), "=r"(r[3]) : "r"(addr));
}
__device__ __forceinline__ void mma16816(float* d, const uint32_t* a, const uint32_t* b) {
    asm volatile("mma.sync.aligned.m16n8k16.row.col.f32.f16.f16.f32 "
        "{%0,%1,%2,%3}, {%4,%5,%6,%7}, {%8,%9}, {%0,%1,%2,%3};"
        : "+f"(d[0]), "+f"(d[1]), "+f"(d[2]), "+f"(d[3])
        : "r"(a[0]), "r"(a[1]), "r"(a[2]), "r"(a[3]), "r"(b[0]), "r"(b[1]));
}
__device__ __forceinline__ uint32_t packh2(float x, float y) {
    __half2 h = __floats2half2_rn(x, y);
    return *(uint32_t*)&h;
}
__device__ __forceinline__ void ex2h2(uint32_t& v) {
    asm("ex2.approx.f16x2 %0, %0;" : "+r"(v));
}

// ---------------------------------------------------------------------------
// One merged prep kernel: converts X, Wq, Wk, Wv, Wo to fp16 + packs bias.
// ---------------------------------------------------------------------------
#define NX4 (MTOT * DIM / 4)     // 1048576
#define NW4 (DIM * DIM / 4)      // 262144

__global__ __launch_bounds__(256)
void prep_all(const float4* __restrict__ X,
              const float4* __restrict__ Wq, const float4* __restrict__ Wk,
              const float4* __restrict__ Wv, const float4* __restrict__ Wo,
              const float* __restrict__ bq, const float* __restrict__ bk,
              const float* __restrict__ bv,
              uint32_t* __restrict__ Xh, uint32_t* __restrict__ Wall,
              uint32_t* __restrict__ Woh, float* __restrict__ bias)
{
    const int gidx = blockIdx.x * 256 + threadIdx.x;

    if (gidx < 3 * DIM) {
        bias[gidx] = (gidx < DIM) ? bq[gidx]
                   : (gidx < 2 * DIM) ? bk[gidx - DIM] : bv[gidx - 2 * DIM];
    }

    const float4* src;
    uint32_t* dst;
    int li;
    if (gidx < NX4) {
        src = X; dst = Xh; li = gidx;
    } else {
        const int i2 = gidx - NX4;
        const int w  = i2 >> 18;             // NW4 = 2^18
        li = i2 & (NW4 - 1);
        if      (w == 0) { src = Wq; dst = Wall; }
        else if (w == 1) { src = Wk; dst = Wall + (size_t)2 * NW4; }
        else if (w == 2) { src = Wv; dst = Wall + (size_t)4 * NW4; }
        else             { src = Wo; dst = Woh; }
    }
    float4 v = src[li];
    dst[2 * li]     = packh2(v.x, v.y);
    dst[2 * li + 1] = packh2(v.z, v.w);
}

// ---------------------------------------------------------------------------
// fp16 GEMM via mma.sync:  C = A @ W^T (+ bias)
// 512 threads/CTA, tile 256x128, warp grid 4x4 (warp tile 64x32), BK=64,
// 3-stage cp.async, occ 1 -> 4 warps/SMSP.
// MODE 0: fp32 C[M,DIM] output
// MODE 1: QKV projection; epilogue scatters per-head fp16 Q,K and transposed V
// ---------------------------------------------------------------------------
#define PADB 144
#define ATILE_B (256 * PADB)                 // 36864 (A: 256 rows)
#define WTILE_B (128 * PADB)                 // 18432 (W: 128 rows)
#define STAGE_B (ATILE_B + WTILE_B)          // 55296
#define NSTAGE 3
#define GEMM_SMEM (NSTAGE * STAGE_B)         // 165888
#define NCHUNK 16                            // K=1024 / 64

__device__ __forceinline__ void load_chunk(uint32_t st,
    const __half* __restrict__ A, const __half* __restrict__ W,
    int k0, int tid)
{
    // A: 256 rows x 64 cols = 2048 x 16B -> 4 per thread
    #pragma unroll
    for (int t = 0; t < 4; t++) {
        const int idx = tid + t * 512;
        const int r = idx >> 3;              // 0..255
        const int q = idx & 7;
        cp16(st + (uint32_t)r * PADB + q * 16, A + (size_t)r * DIM + k0 + q * 8);
    }
    // W: 128 rows x 64 cols = 1024 x 16B -> 2 per thread
    #pragma unroll
    for (int t = 0; t < 2; t++) {
        const int idx = tid + t * 512;
        const int r = idx >> 3;              // 0..127
        const int q = idx & 7;
        cp16(st + ATILE_B + (uint32_t)r * PADB + q * 16,
             W + (size_t)r * DIM + k0 + q * 8);
    }
    cp_commit();
}

template <int MODE>
__global__ __launch_bounds__(512)
void gemm_tc(const __half* __restrict__ Ag, const __half* __restrict__ Wg,
             const float* __restrict__ bias, float* __restrict__ C,
             __half* __restrict__ Qp, __half* __restrict__ Kp,
             __half* __restrict__ Vtp)
{
    extern __shared__ char smr[];
    const uint32_t sb = smem_u32(smr);
    const int tid  = threadIdx.x;
    const int wid  = tid >> 5;
    const int lane = tid & 31;
    const int wr = wid >> 2;                 // 0..3 (M)
    const int wc = wid & 3;                  // 0..3 (N)
    const int m0 = blockIdx.y * 256;
    const int n0 = blockIdx.x * 128;

    const __half* A = Ag + (size_t)m0 * DIM;
    const __half* W = Wg + (size_t)n0 * DIM;

    float c[4][4][4];
    #pragma unroll
    for (int i = 0; i < 4; i++)
        #pragma unroll
        for (int j = 0; j < 4; j++)
            #pragma unroll
            for (int e = 0; e < 4; e++) c[i][j][e] = 0.f;

    load_chunk(sb,           A, W, 0,  tid);
    load_chunk(sb + STAGE_B, A, W, 64, tid);

    const uint32_t a_row  = (uint32_t)(lane & 15);
    const uint32_t a_koff = (uint32_t)((lane >> 4) * 8);
    const uint32_t b_row  = (uint32_t)(((lane >> 4) << 3) + (lane & 7));
    const uint32_t b_koff = (uint32_t)(((lane >> 3) & 1) * 8);

    for (int ch = 0; ch < NCHUNK; ch++) {
        cp_wait1();
        __syncthreads();

        const int nc = ch + 2;
        if (nc < NCHUNK)
            load_chunk(sb + (uint32_t)(nc % NSTAGE) * STAGE_B, A, W, nc * 64, tid);
        else
            cp_commit();

        const uint32_t sA = sb + (uint32_t)(ch % NSTAGE) * STAGE_B;
        const uint32_t sW = sA + ATILE_B;

        #pragma unroll
        for (int h = 0; h < 4; h++) {
            const uint32_t acol = (h * 16 + a_koff) * 2;
            const uint32_t bcol = (h * 16 + b_koff) * 2;
            uint32_t a[4][4], b[2][4];
            #pragma unroll
            for (int i = 0; i < 4; i++)
                ldsm4(a[i], sA + (wr * 64 + i * 16 + a_row) * PADB + acol);
            #pragma unroll
            for (int jp = 0; jp < 2; jp++)
                ldsm4(b[jp], sW + (wc * 32 + jp * 16 + b_row) * PADB + bcol);
            #pragma unroll
            for (int i = 0; i < 4; i++) {
                mma16816(c[i][0], a[i], &b[0][0]);
                mma16816(c[i][1], a[i], &b[0][2]);
                mma16816(c[i][2], a[i], &b[1][0]);
                mma16816(c[i][3], a[i], &b[1][2]);
            }
        }
    }
    cp_wait0();

    const int g   = lane >> 2;
    const int tig = lane & 3;

    if (MODE == 0) {
        #pragma unroll
        for (int i = 0; i < 4; i++) {
            const int r0 = m0 + wr * 64 + i * 16 + g;
            #pragma unroll
            for (int j = 0; j < 4; j++) {
                const int cb = n0 + wc * 32 + j * 8 + 2 * tig;
                const float b0 = bias[cb], b1 = bias[cb + 1];
                float2 v0 = make_float2(c[i][j][0] + b0, c[i][j][1] + b1);
                float2 v1 = make_float2(c[i][j][2] + b0, c[i][j][3] + b1);
                *(float2*)(C + (size_t)r0 * DIM + cb)       = v0;
                *(float2*)(C + (size_t)(r0 + 8) * DIM + cb) = v1;
            }
        }
    } else {
        const int sec = n0 >> 10;            // 0=Q, 1=K, 2=V
        const int b   = m0 >> 11;            // batch (m0 multiple of 256)
        const int sb0 = (m0 & 2047) + wr * 64 + g;
        #pragma unroll
        for (int i = 0; i < 4; i++) {
            const int s = sb0 + i * 16;
            #pragma unroll
            for (int j = 0; j < 4; j++) {
                const int col = n0 + wc * 32 + j * 8 + 2 * tig;
                const int lc  = col & 1023;
                const int h   = lc >> 6;
                const int d   = lc & 63;
                const int bh  = b * NH + h;
                const float b0 = bias[col], b1 = bias[col + 1];
                const float v00 = c[i][j][0] + b0, v01 = c[i][j][1] + b1;
                const float v10 = c[i][j][2] + b0, v11 = c[i][j][3] + b1;
                if (sec < 2) {
                    __half* D = (sec == 0) ? Qp : Kp;
                    const size_t o0 = ((size_t)bh * SEQ + s) * HDIM + d;
                    *(uint32_t*)(D + o0)            = packh2(v00, v01);
                    *(uint32_t*)(D + o0 + 8 * HDIM) = packh2(v10, v11);
                } else {
                    const size_t vb0 = ((size_t)bh * HDIM + d) * SEQ + s;
                    const size_t vb1 = vb0 + SEQ;
                    Vtp[vb0]     = __float2half_rn(v00);
                    Vtp[vb1]     = __float2half_rn(v01);
                    Vtp[vb0 + 8] = __float2half_rn(v10);
                    Vtp[vb1 + 8] = __float2half_rn(v11);
                }
            }
        }
    }
}

// ---------------------------------------------------------------------------
// Causal flash attention on fp16 HMMA (unchanged from R9).
// ---------------------------------------------------------------------------
#define APAD 144
#define ATT_Q_BYTES (128 * APAD)
#define ATT_T_BYTES (64 * APAD)
#define ATT_STAGE   (2 * ATT_T_BYTES)
#define ATT_NST     3
#define ATT_SMEM    (ATT_Q_BYTES + ATT_NST * ATT_STAGE)   // 73728

__device__ __forceinline__ void load_kv(uint32_t dst,
    const __half* __restrict__ Kp, const __half* __restrict__ Vp,
    int j, int tid)
{
    const int r  = tid >> 2;
    const int c0 = tid & 3;
    const uint32_t ro = (uint32_t)r * APAD;
    const size_t kg = (size_t)(j * 64 + r) * HDIM;
    const size_t vg = (size_t)r * SEQ + j * 64;
    cp16(dst + ro + c0 * 16,                 Kp + kg + c0 * 8);
    cp16(dst + ro + (c0 + 4) * 16,           Kp + kg + (c0 + 4) * 8);
    cp16(dst + ATT_T_BYTES + ro + c0 * 16,       Vp + vg + c0 * 8);
    cp16(dst + ATT_T_BYTES + ro + (c0 + 4) * 16, Vp + vg + (c0 + 4) * 8);
    cp_commit();
}

__device__ __forceinline__ void attn_one_qtile(
    int qt, int b, int h,
    const __half* __restrict__ Q, const __half* __restrict__ Kp,
    const __half* __restrict__ Vp, __half* __restrict__ O,
    uint32_t sQ, uint32_t skv, int tid)
{
    const int w    = tid >> 5;
    const int lane = tid & 31;
    const int g    = lane >> 2;
    const int t    = lane & 3;
    const int bh   = b * NH + h;

    const __half* Qp = Q + ((size_t)bh * SEQ + qt * 128) * HDIM;

    #pragma unroll
    for (int i = 0; i < 4; i++) {
        int idx = tid + i * 256;
        int r = idx >> 3, q = idx & 7;
        cp16(sQ + (uint32_t)r * APAD + q * 16, Qp + (size_t)r * HDIM + q * 8);
    }
    cp_commit();
    load_kv(skv,             Kp, Vp, 0, tid);
    load_kv(skv + ATT_STAGE, Kp, Vp, 1, tid);
    cp_wait2();
    __syncthreads();

    const uint32_t a_row  = (uint32_t)(lane & 15);
    const uint32_t a_koff = (uint32_t)((lane >> 4) * 8);
    const uint32_t b_row  = (uint32_t)(((lane >> 4) << 3) + (lane & 7));
    const uint32_t b_koff = (uint32_t)(((lane >> 3) & 1) * 8);

    const uint32_t bones[2] = { (lane < 4) ? 0x3C003C00u : 0u,
                                (lane < 4) ? 0x3C003C00u : 0u };

    uint32_t qf[4][4];
    #pragma unroll
    for (int h4 = 0; h4 < 4; h4++)
        ldsm4(qf[h4], sQ + (w * 16 + a_row) * APAD + (h4 * 16 + a_koff) * 2);

    float o[8][4];
    #pragma unroll
    for (int nb = 0; nb < 8; nb++)
        #pragma unroll
        for (int e = 0; e < 4; e++) o[nb][e] = 0.f;
    float lac[4] = {0.f, 0.f, 0.f, 0.f};
    float mi0 = -1e30f, mi1 = -1e30f;

    const int sq0 = qt * 128 + w * 16 + g;
    const int njt = 2 * qt + 2;
    const float CE = 0.125f * 1.4426950408889634f;

    for (int j = 0; j < njt; j++) {
        cp_wait1();
        __syncthreads();

        if (j + 2 < njt)
            load_kv(skv + ((j + 2) % ATT_NST) * ATT_STAGE, Kp, Vp, j + 2, tid);
        else
            cp_commit();

        const uint32_t sK = skv + (j % ATT_NST) * ATT_STAGE;
        const uint32_t sV = sK + ATT_T_BYTES;

        float s[8][4];
        #pragma unroll
        for (int nb = 0; nb < 8; nb++)
            #pragma unroll
            for (int e = 0; e < 4; e++) s[nb][e] = 0.f;

        #pragma unroll
        for (int h4 = 0; h4 < 4; h4++) {
            const uint32_t col = (h4 * 16 + b_koff) * 2;
            #pragma unroll
            for (int jp = 0; jp < 4; jp++) {
                uint32_t kb[4];
                ldsm4(kb, sK + (jp * 16 + b_row) * APAD + col);
                mma16816(s[2 * jp],     qf[h4], kb);
                mma16816(s[2 * jp + 1], qf[h4], kb + 2);
            }
        }

        const int kb0 = j * 64 + 2 * t;
        #pragma unroll
        for (int nb = 0; nb < 8; nb++) {
            const int c0 = kb0 + nb * 8;
            if (c0     > sq0)     s[nb][0] = -1e30f;
            if (c0 + 1 > sq0)     s[nb][1] = -1e30f;
            if (c0     > sq0 + 8) s[nb][2] = -1e30f;
            if (c0 + 1 > sq0 + 8) s[nb][3] = -1e30f;
        }

        float m0 = -1e30f, m1 = -1e30f;
        #pragma unroll
        for (int nb = 0; nb < 8; nb++) {
            m0 = fmaxf(m0, fmaxf(s[nb][0], s[nb][1]));
            m1 = fmaxf(m1, fmaxf(s[nb][2], s[nb][3]));
        }
        m0 = fmaxf(m0, __shfl_xor_sync(0xFFFFFFFFu, m0, 1));
        m0 = fmaxf(m0, __shfl_xor_sync(0xFFFFFFFFu, m0, 2));
        m1 = fmaxf(m1, __shfl_xor_sync(0xFFFFFFFFu, m1, 1));
        m1 = fmaxf(m1, __shfl_xor_sync(0xFFFFFFFFu, m1, 2));
        const float mn0 = fmaxf(mi0, m0), mn1 = fmaxf(mi1, m1);
        const float corr0 = exp2f((mi0 - mn0) * CE);
        const float corr1 = exp2f((mi1 - mn1) * CE);
        mi0 = mn0; mi1 = mn1;

        #pragma unroll
        for (int nb = 0; nb < 8; nb++) {
            o[nb][0] *= corr0; o[nb][1] *= corr0;
            o[nb][2] *= corr1; o[nb][3] *= corr1;
        }
        lac[0] *= corr0; lac[1] *= corr0;
        lac[2] *= corr1; lac[3] *= corr1;

        uint32_t pf[4][4];
        #pragma unroll
        for (int h4 = 0; h4 < 4; h4++) {
            pf[h4][0] = packh2((s[2 * h4][0]     - mn0) * CE, (s[2 * h4][1]     - mn0) * CE);
            pf[h4][1] = packh2((s[2 * h4][2]     - mn1) * CE, (s[2 * h4][3]     - mn1) * CE);
            pf[h4][2] = packh2((s[2 * h4 + 1][0] - mn0) * CE, (s[2 * h4 + 1][1] - mn0) * CE);
            pf[h4][3] = packh2((s[2 * h4 + 1][2] - mn1) * CE, (s[2 * h4 + 1][3] - mn1) * CE);
            ex2h2(pf[h4][0]); ex2h2(pf[h4][1]);
            ex2h2(pf[h4][2]); ex2h2(pf[h4][3]);
        }

        #pragma unroll
        for (int h4 = 0; h4 < 4; h4++) {
            const uint32_t col = (h4 * 16 + b_koff) * 2;
            #pragma unroll
            for (int jp = 0; jp < 4; jp++) {
                uint32_t vb[4];
                ldsm4(vb, sV + (jp * 16 + b_row) * APAD + col);
                mma16816(o[2 * jp],     pf[h4], vb);
                mma16816(o[2 * jp + 1], pf[h4], vb + 2);
            }
            mma16816(lac, pf[h4], bones);
        }
        __syncthreads();
    }

    cp_wait0();
    __syncthreads();

    const int ql = lane & ~3;
    const float li0 = __shfl_sync(0xFFFFFFFFu, lac[0], ql);
    const float li1 = __shfl_sync(0xFFFFFFFFu, lac[2], ql);
    const float inv0 = 1.f / li0;
    const float inv1 = 1.f / li1;
    const size_t ob = (size_t)(b * SEQ + sq0) * DIM + h * HDIM;
    #pragma unroll
    for (int nb = 0; nb < 8; nb++) {
        const int d = nb * 8 + 2 * t;
        *(uint32_t*)(O + ob + d)           = packh2(o[nb][0] * inv0, o[nb][1] * inv0);
        *(uint32_t*)(O + ob + 8 * DIM + d) = packh2(o[nb][2] * inv1, o[nb][3] * inv1);
    }
}

__global__ __launch_bounds__(256, 2)
void attn_mma(const __half* __restrict__ Q, const __half* __restrict__ K,
              const __half* __restrict__ Vt, __half* __restrict__ O)
{
    extern __shared__ char smr[];
    const uint32_t sbse = smem_u32(smr);
    const uint32_t sQ  = sbse;
    const uint32_t skv = sbse + ATT_Q_BYTES;

    const int tid = threadIdx.x;
    const int bx  = blockIdx.x;          // 0..7
    const int bh  = blockIdx.y;
    const int b   = bh >> 4;
    const int h   = bh & 15;

    const __half* Kp = K + (size_t)bh * SEQ * HDIM;
    const __half* Vp = Vt + (size_t)bh * HDIM * SEQ;

    attn_one_qtile(15 - bx, b, h, Q, Kp, Vp, O, sQ, skv, tid);
    attn_one_qtile(bx,      b, h, Q, Kp, Vp, O, sQ, skv, tid);
}

// ---------------------------------------------------------------------------
// Launch
// ---------------------------------------------------------------------------
extern "C" void kernel_launch(void* const* d_in, const int* in_sizes, int n_in,
                              void* d_out, int out_size)
{
    const float* X  = (const float*)d_in[0];
    const float* Wq = (const float*)d_in[1];
    const float* bq = (const float*)d_in[2];
    const float* Wk = (const float*)d_in[3];
    const float* bk = (const float*)d_in[4];
    const float* Wv = (const float*)d_in[5];
    const float* bv = (const float*)d_in[6];
    const float* Wo = (const float*)d_in[7];
    const float* bo = (const float*)d_in[8];
    float* out = (float*)d_out;

    float* bias;
    cudaGetSymbolAddress((void**)&bias, g_bias);

    __half *Xh, *Oh, *Wall, *Woh, *Qp, *Kp, *Vtp;
    cudaGetSymbolAddress((void**)&Xh, g_Xh);
    cudaGetSymbolAddress((void**)&Oh, g_Oh);
    cudaGetSymbolAddress((void**)&Wall, g_Wall);
    cudaGetSymbolAddress((void**)&Woh, g_Wo_h);
    cudaGetSymbolAddress((void**)&Qp, g_Q);
    cudaGetSymbolAddress((void**)&Kp, g_K);
    cudaGetSymbolAddress((void**)&Vtp, g_Vt);

    cudaFuncSetAttribute(gemm_tc<0>, cudaFuncAttributeMaxDynamicSharedMemorySize, GEMM_SMEM);
    cudaFuncSetAttribute(gemm_tc<1>, cudaFuncAttributeMaxDynamicSharedMemorySize, GEMM_SMEM);
    cudaFuncSetAttribute(attn_mma, cudaFuncAttributeMaxDynamicSharedMemorySize, ATT_SMEM);

    prep_all<<<(NX4 + 4 * NW4) / 256, 256>>>(
        (const float4*)X, (const float4*)Wq, (const float4*)Wk,
        (const float4*)Wv, (const float4*)Wo, bq, bk, bv,
        (uint32_t*)Xh, (uint32_t*)Wall, (uint32_t*)Woh, bias);

    // fused QKV projection: grid (24, 16), 512-thread CTAs
    gemm_tc<1><<<dim3(3 * DIM / 128, MTOT / 256), 512, GEMM_SMEM>>>(
        Xh, Wall, bias, nullptr, Qp, Kp, Vtp);

    attn_mma<<<dim3(8, BATCH * NH), 256, ATT_SMEM>>>(Qp, Kp, Vtp, Oh);

    // output projection: grid (8, 16), single wave
    gemm_tc<0><<<dim3(DIM / 128, MTOT / 256), 512, GEMM_SMEM>>>(
        Oh, Woh, bo, out, nullptr, nullptr, nullptr);
}